// round 6
// baseline (speedup 1.0000x reference)
#include <cuda_runtime.h>
#include <cstdint>

#define NNODES 100000
#define MAXE   1000000

// ---------------- scratch (static __device__ globals; no allocation) -------
__device__ __align__(16) float4 g_bufA[NNODES * 32];   // 100000 x 128 floats
__device__ __align__(16) float4 g_bufB[NNODES * 32];   // 100000 x 128 floats
__device__ __align__(16) float4 g_hw3 [NNODES * 10];   // 100000 x 40 floats
__device__ __align__(16) float4 g_agg3[NNODES * 10];   // 100000 x 40 floats
__device__ float g_dinv[NNODES];
__device__ int   g_icnt[NNODES];
__device__ int   g_fc  [NNODES];
__device__ int   g_rs  [NNODES + 1];
__device__ int   g_perm[MAXE];
__device__ int   g_bsum[512];
__device__ int   g_boff[512];
__device__ float g_sums[512];
__device__ __align__(16) float g_scale[256];
__device__ __align__(16) float g_shift[256];
__device__ unsigned g_keys[4];

#define SCAN_BLOCKS 391

// ---------------- threefry2x32 (JAX-exact, 20 rounds) ----------------------
__device__ __forceinline__ void tf_round(uint32_t &x0, uint32_t &x1, int r) {
    x0 += x1;
    x1 = __funnelshift_l(x1, x1, r);
    x1 ^= x0;
}

__device__ __forceinline__ uint2 tf_full(uint32_t k0, uint32_t k1, uint32_t x0, uint32_t x1) {
    uint32_t k2 = k0 ^ k1 ^ 0x1BD11BDAu;
    x0 += k0; x1 += k1;
    tf_round(x0,x1,13); tf_round(x0,x1,15); tf_round(x0,x1,26); tf_round(x0,x1,6);
    x0 += k1; x1 += k2 + 1u;
    tf_round(x0,x1,17); tf_round(x0,x1,29); tf_round(x0,x1,16); tf_round(x0,x1,24);
    x0 += k2; x1 += k0 + 2u;
    tf_round(x0,x1,13); tf_round(x0,x1,15); tf_round(x0,x1,26); tf_round(x0,x1,6);
    x0 += k0; x1 += k1 + 3u;
    tf_round(x0,x1,17); tf_round(x0,x1,29); tf_round(x0,x1,16); tf_round(x0,x1,24);
    x0 += k1; x1 += k2 + 4u;
    tf_round(x0,x1,13); tf_round(x0,x1,15); tf_round(x0,x1,26); tf_round(x0,x1,6);
    x0 += k2; x1 += k0 + 5u;
    return make_uint2(x0, x1);
}

__device__ __forceinline__ uint32_t tf_bits_xor(uint32_t k0, uint32_t k1, uint32_t k2, uint32_t ctr) {
    uint32_t x0 = k0;
    uint32_t x1 = ctr + k1;
    tf_round(x0,x1,13); tf_round(x0,x1,15); tf_round(x0,x1,26); tf_round(x0,x1,6);
    x0 += k1; x1 += k2 + 1u;
    tf_round(x0,x1,17); tf_round(x0,x1,29); tf_round(x0,x1,16); tf_round(x0,x1,24);
    x0 += k2; x1 += k0 + 2u;
    tf_round(x0,x1,13); tf_round(x0,x1,15); tf_round(x0,x1,26); tf_round(x0,x1,6);
    x0 += k0; x1 += k1 + 3u;
    tf_round(x0,x1,17); tf_round(x0,x1,29); tf_round(x0,x1,16); tf_round(x0,x1,24);
    x0 += k1; x1 += k2 + 4u;
    tf_round(x0,x1,13); tf_round(x0,x1,15); tf_round(x0,x1,26); tf_round(x0,x1,6);
    x0 += k2; x1 += k0 + 5u;
    return x0 ^ x1;
}

__global__ void k_keys() {
    if (threadIdx.x == 0) {
        uint2 a = tf_full(0u, 42u, 0u, 0u);
        uint2 b = tf_full(0u, 42u, 0u, 1u);
        g_keys[0] = a.x; g_keys[1] = a.y;
        g_keys[2] = b.x; g_keys[3] = b.y;
    }
}

// ---------------- graph preprocessing --------------------------------------
__global__ void k_zero() {
    int i = blockIdx.x * 256 + threadIdx.x;
    if (i < NNODES) { g_icnt[i] = 0; g_fc[i] = 0; }
    if (i < 512)    g_sums[i] = 0.f;
}

__global__ void k_degree(const int* __restrict__ dst, int E) {
    int e = blockIdx.x * 256 + threadIdx.x;
    if (e < E) atomicAdd(&g_icnt[dst[e]], 1);
}

__global__ void k_dinv() {
    int i = blockIdx.x * 256 + threadIdx.x;
    if (i < NNODES) g_dinv[i] = rsqrtf((float)g_icnt[i] + 1.0f);
}

__global__ __launch_bounds__(256) void k_scan_local() {
    __shared__ int s[256];
    int t = threadIdx.x;
    int i = blockIdx.x * 256 + t;
    int v = (i < NNODES) ? g_icnt[i] : 0;
    s[t] = v;
    __syncthreads();
#pragma unroll
    for (int off = 1; off < 256; off <<= 1) {
        int add = (t >= off) ? s[t - off] : 0;
        __syncthreads();
        s[t] += add;
        __syncthreads();
    }
    if (i < NNODES) g_rs[i] = s[t] - v;
    if (t == 255) g_bsum[blockIdx.x] = s[255];
}

__global__ __launch_bounds__(512) void k_scan_block() {
    __shared__ int s[512];
    int t = threadIdx.x;
    int v = (t < SCAN_BLOCKS) ? g_bsum[t] : 0;
    s[t] = v;
    __syncthreads();
#pragma unroll
    for (int off = 1; off < 512; off <<= 1) {
        int add = (t >= off) ? s[t - off] : 0;
        __syncthreads();
        s[t] += add;
        __syncthreads();
    }
    g_boff[t] = s[t] - v;
}

__global__ void k_scan_add(int E) {
    int i = blockIdx.x * 256 + threadIdx.x;
    if (i < NNODES) g_rs[i] += g_boff[blockIdx.x];
    if (i == NNODES) g_rs[NNODES] = E;
}

__global__ void k_fill(const int* __restrict__ src, const int* __restrict__ dst, int E) {
    int e = blockIdx.x * 256 + threadIdx.x;
    if (e >= E) return;
    int d = dst[e];
    int pos = g_rs[d] + atomicAdd(&g_fc[d], 1);
    g_perm[pos] = src[e];
}

// ---------------- TF32 split-MMA GEMM: C[M x NC] = A[M x 128] * B[128 x NC]
// 3xTF32: a=ahi+alo, b=bhi+blo; D += ahi*bhi + alo*bhi + ahi*blo (err ~2^-22)
__device__ __forceinline__ uint32_t f2tf32(float x) {
    uint32_t r;
    asm("cvt.rna.tf32.f32 %0, %1;" : "=r"(r) : "f"(x));
    return r;
}

#define MMA_TF32(c0,c1,c2,c3, a0,a1,a2,a3, b0,b1)                              \
    asm volatile("mma.sync.aligned.m16n8k8.row.col.f32.tf32.tf32.f32 "         \
                 "{%0,%1,%2,%3}, {%4,%5,%6,%7}, {%8,%9}, {%0,%1,%2,%3};"       \
                 : "+f"(c0), "+f"(c1), "+f"(c2), "+f"(c3)                      \
                 : "r"(a0), "r"(a1), "r"(a2), "r"(a3), "r"(b0), "r"(b1))

template<int NTILES>
__global__ __launch_bounds__(256) void sgemm_tf32(
    const float* __restrict__ A, const float* __restrict__ B,
    float* __restrict__ C, int M, int NC)
{
    __shared__ __align__(16) float As[16][136];   // [k][row], stride 136 -> conflict-free frags
    __shared__ __align__(16) float Bh[16][136];   // tf32-hi of B, [k][col]
    __shared__ __align__(16) float Bl[16][136];   // tf32-lo of B
    int tid  = threadIdx.x;
    int warp = tid >> 5, lane = tid & 31;
    int gid  = lane >> 2, ctid = lane & 3;
    int row0 = blockIdx.x * 128;
    int wr   = warp * 16;                          // in-block row base for this warp

    float c[NTILES][4];
#pragma unroll
    for (int nt = 0; nt < NTILES; nt++)
#pragma unroll
        for (int j = 0; j < 4; j++) c[nt][j] = 0.f;

    int a_row = tid >> 1;            // 0..127
    int a_k8  = (tid & 1) * 8;       // 0 or 8
    int b_k   = tid >> 4;            // 0..15
    int b_c8  = (tid & 15) * 8;      // 0..120

    for (int k0 = 0; k0 < 128; k0 += 16) {
        // stage A (128 rows x 16 k)
        float4 av0 = make_float4(0.f,0.f,0.f,0.f), av1 = av0;
        int gr = row0 + a_row;
        if (gr < M) {
            av0 = *(const float4*)(A + gr * 128 + k0 + a_k8);
            av1 = *(const float4*)(A + gr * 128 + k0 + a_k8 + 4);
        }
        As[a_k8 + 0][a_row] = av0.x; As[a_k8 + 1][a_row] = av0.y;
        As[a_k8 + 2][a_row] = av0.z; As[a_k8 + 3][a_row] = av0.w;
        As[a_k8 + 4][a_row] = av1.x; As[a_k8 + 5][a_row] = av1.y;
        As[a_k8 + 6][a_row] = av1.z; As[a_k8 + 7][a_row] = av1.w;

        // stage B hi/lo (16 k x NC cols, zero-padded to 128)
#pragma unroll
        for (int j = 0; j < 8; j++) {
            int cc = b_c8 + j;
            float bv = (cc < NC) ? B[(k0 + b_k) * NC + cc] : 0.f;
            float hf = __uint_as_float(f2tf32(bv));
            Bh[b_k][cc] = hf;
            Bl[b_k][cc] = __uint_as_float(f2tf32(bv - hf));
        }
        __syncthreads();

#pragma unroll
        for (int kk = 0; kk < 16; kk += 8) {
            float a0 = As[kk + ctid    ][wr + gid];
            float a1 = As[kk + ctid    ][wr + gid + 8];
            float a2 = As[kk + ctid + 4][wr + gid];
            float a3 = As[kk + ctid + 4][wr + gid + 8];
            uint32_t ah0 = f2tf32(a0), ah1 = f2tf32(a1), ah2 = f2tf32(a2), ah3 = f2tf32(a3);
            uint32_t al0 = f2tf32(a0 - __uint_as_float(ah0));
            uint32_t al1 = f2tf32(a1 - __uint_as_float(ah1));
            uint32_t al2 = f2tf32(a2 - __uint_as_float(ah2));
            uint32_t al3 = f2tf32(a3 - __uint_as_float(ah3));
#pragma unroll
            for (int nt = 0; nt < NTILES; nt++) {
                int cb = nt * 8 + gid;
                uint32_t bh0 = __float_as_uint(Bh[kk + ctid    ][cb]);
                uint32_t bh1 = __float_as_uint(Bh[kk + ctid + 4][cb]);
                uint32_t bl0 = __float_as_uint(Bl[kk + ctid    ][cb]);
                uint32_t bl1 = __float_as_uint(Bl[kk + ctid + 4][cb]);
                MMA_TF32(c[nt][0], c[nt][1], c[nt][2], c[nt][3],
                         ah0, ah1, ah2, ah3, bh0, bh1);
                MMA_TF32(c[nt][0], c[nt][1], c[nt][2], c[nt][3],
                         al0, al1, al2, al3, bh0, bh1);
                MMA_TF32(c[nt][0], c[nt][1], c[nt][2], c[nt][3],
                         ah0, ah1, ah2, ah3, bl0, bl1);
            }
        }
        __syncthreads();
    }

    int r0 = row0 + wr + gid;
    int r1 = r0 + 8;
#pragma unroll
    for (int nt = 0; nt < NTILES; nt++) {
        int cc = nt * 8 + ctid * 2;
        if (r0 < M) *(float2*)(C + r0 * NC + cc) = make_float2(c[nt][0], c[nt][1]);
        if (r1 < M) *(float2*)(C + r1 * NC + cc) = make_float2(c[nt][2], c[nt][3]);
    }
}

// ---------------- CSR SpMM (no atomics): agg = Anorm*hw + self + bias ------
__global__ __launch_bounds__(256) void spmm128(
    const float4* __restrict__ hw, float4* __restrict__ agg,
    const float* __restrict__ bias)
{
    int row = blockIdx.x * 8 + (threadIdx.x >> 5);
    if (row >= NNODES) return;
    int lane = threadIdx.x & 31;
    int beg = __ldg(&g_rs[row]);
    int end = __ldg(&g_rs[row + 1]);
    float di = g_dinv[row];
    float di2 = di * di;

    float4 self = __ldg(hw + row * 32 + lane);
    float4 b = ((const float4*)bias)[lane];
    float4 acc  = make_float4(fmaf(self.x, di2, b.x), fmaf(self.y, di2, b.y),
                              fmaf(self.z, di2, b.z), fmaf(self.w, di2, b.w));
    float4 acc2 = make_float4(0.f, 0.f, 0.f, 0.f);

    int j = beg;
    for (; j + 1 < end; j += 2) {
        int s0 = __ldg(&g_perm[j]);
        int s1 = __ldg(&g_perm[j + 1]);
        float n0 = __ldg(&g_dinv[s0]) * di;
        float n1 = __ldg(&g_dinv[s1]) * di;
        float4 v0 = __ldg(hw + s0 * 32 + lane);
        float4 v1 = __ldg(hw + s1 * 32 + lane);
        acc.x  = fmaf(v0.x, n0, acc.x);  acc.y  = fmaf(v0.y, n0, acc.y);
        acc.z  = fmaf(v0.z, n0, acc.z);  acc.w  = fmaf(v0.w, n0, acc.w);
        acc2.x = fmaf(v1.x, n1, acc2.x); acc2.y = fmaf(v1.y, n1, acc2.y);
        acc2.z = fmaf(v1.z, n1, acc2.z); acc2.w = fmaf(v1.w, n1, acc2.w);
    }
    if (j < end) {
        int s0 = __ldg(&g_perm[j]);
        float n0 = __ldg(&g_dinv[s0]) * di;
        float4 v0 = __ldg(hw + s0 * 32 + lane);
        acc.x = fmaf(v0.x, n0, acc.x); acc.y = fmaf(v0.y, n0, acc.y);
        acc.z = fmaf(v0.z, n0, acc.z); acc.w = fmaf(v0.w, n0, acc.w);
    }
    agg[row * 32 + lane] = make_float4(acc.x + acc2.x, acc.y + acc2.y,
                                       acc.z + acc2.z, acc.w + acc2.w);
}

__global__ __launch_bounds__(256) void spmm40(
    const float4* __restrict__ hw, float4* __restrict__ agg,
    const float* __restrict__ bias)
{
    int row = blockIdx.x * 8 + (threadIdx.x >> 5);
    if (row >= NNODES) return;
    int lane = threadIdx.x & 31;
    if (lane >= 10) return;
    int beg = __ldg(&g_rs[row]);
    int end = __ldg(&g_rs[row + 1]);
    float di = g_dinv[row];
    float di2 = di * di;

    float4 self = __ldg(hw + row * 10 + lane);
    float4 b = ((const float4*)bias)[lane];
    float4 acc = make_float4(fmaf(self.x, di2, b.x), fmaf(self.y, di2, b.y),
                             fmaf(self.z, di2, b.z), fmaf(self.w, di2, b.w));
    for (int j = beg; j < end; j++) {
        int s = __ldg(&g_perm[j]);
        float n = __ldg(&g_dinv[s]) * di;
        float4 v = __ldg(hw + s * 10 + lane);
        acc.x = fmaf(v.x, n, acc.x); acc.y = fmaf(v.y, n, acc.y);
        acc.z = fmaf(v.z, n, acc.z); acc.w = fmaf(v.w, n, acc.w);
    }
    agg[row * 10 + lane] = acc;
}

// ---------------- batchnorm stats + finalize -------------------------------
__global__ __launch_bounds__(256) void k_bnstats(const float* __restrict__ h,
                                                 float* __restrict__ sums) {
    __shared__ float ss[256], sq[256];
    int tid = threadIdx.x;
    int c = tid & 127;
    int half = tid >> 7;
    int rbeg = blockIdx.x * 250;
    float s = 0.f, q = 0.f;
    for (int r = rbeg + half; r < rbeg + 250; r += 2) {
        float v = h[r * 128 + c];
        s += v;
        q = fmaf(v, v, q);
    }
    ss[tid] = s; sq[tid] = q;
    __syncthreads();
    if (half == 0) {
        atomicAdd(&sums[c],       ss[tid] + ss[tid + 128]);
        atomicAdd(&sums[128 + c], sq[tid] + sq[tid + 128]);
    }
}

__global__ void k_bnfinal(const float* __restrict__ sums,
                          const float* __restrict__ gamma, const float* __restrict__ beta,
                          float* __restrict__ sc, float* __restrict__ sh) {
    int c = threadIdx.x;
    const float inv_n = 1.0f / (float)NNODES;
    float mean = sums[c] * inv_n;
    float var  = sums[128 + c] * inv_n - mean * mean;
    var = fmaxf(var, 0.f);
    float rstd = rsqrtf(var + 1e-5f);
    float a = gamma[c] * rstd;
    sc[c] = a;
    sh[c] = beta[c] - mean * a;
}

// ---------------- fused BN + ReLU + exact threefry dropout -----------------
__global__ __launch_bounds__(256) void k_bndrop(
    const float4* __restrict__ in, float4* __restrict__ out,
    const float* __restrict__ sc, const float* __restrict__ sh,
    int layer, int n4)
{
    int t = blockIdx.x * 256 + threadIdx.x;
    if (t >= n4) return;
    uint32_t k0 = g_keys[layer * 2 + 0];
    uint32_t k1 = g_keys[layer * 2 + 1];
    uint32_t k2 = k0 ^ k1 ^ 0x1BD11BDAu;

    int c = (t & 31) * 4;
    float4 v = in[t];
    float4 a = *(const float4*)(sc + c);
    float4 b = *(const float4*)(sh + c);

    float r0 = fmaxf(fmaf(v.x, a.x, b.x), 0.f);
    float r1 = fmaxf(fmaf(v.y, a.y, b.y), 0.f);
    float r2 = fmaxf(fmaf(v.z, a.z, b.z), 0.f);
    float r3 = fmaxf(fmaf(v.w, a.w, b.w), 0.f);

    uint32_t i0 = (uint32_t)t * 4u;
    uint32_t m0 = tf_bits_xor(k0, k1, k2, i0 + 0u);
    uint32_t m1 = tf_bits_xor(k0, k1, k2, i0 + 1u);
    uint32_t m2 = tf_bits_xor(k0, k1, k2, i0 + 2u);
    uint32_t m3 = tf_bits_xor(k0, k1, k2, i0 + 3u);

    v.x = (m0 & 0x80000000u) ? 0.f : r0 + r0;
    v.y = (m1 & 0x80000000u) ? 0.f : r1 + r1;
    v.z = (m2 & 0x80000000u) ? 0.f : r2 + r2;
    v.w = (m3 & 0x80000000u) ? 0.f : r3 + r3;
    out[t] = v;
}

// ---------------- log_softmax over 40 cols (warp per row) ------------------
__global__ __launch_bounds__(256) void k_logsoftmax(const float* __restrict__ in,
                                                    float* __restrict__ out, int n) {
    int r = blockIdx.x * 8 + (threadIdx.x >> 5);
    if (r >= n) return;
    int lane = threadIdx.x & 31;
    float v0 = __ldg(in + r * 40 + lane);
    float v1 = (lane < 8) ? __ldg(in + r * 40 + 32 + lane) : -3.4e38f;
    float mx = fmaxf(v0, v1);
#pragma unroll
    for (int o = 16; o; o >>= 1) mx = fmaxf(mx, __shfl_xor_sync(0xffffffffu, mx, o));
    float s = expf(v0 - mx) + ((lane < 8) ? expf(v1 - mx) : 0.f);
#pragma unroll
    for (int o = 16; o; o >>= 1) s += __shfl_xor_sync(0xffffffffu, s, o);
    float l = mx + logf(s);
    out[r * 40 + lane] = v0 - l;
    if (lane < 8) out[r * 40 + 32 + lane] = v1 - l;
}

// ---------------- launch ---------------------------------------------------
extern "C" void kernel_launch(void* const* d_in, const int* in_sizes, int n_in,
                              void* d_out, int out_size) {
    const float* x   = (const float*)d_in[0];
    const int*   ei  = (const int*)  d_in[1];
    const float* W1  = (const float*)d_in[2];
    const float* b1  = (const float*)d_in[3];
    const float* g1  = (const float*)d_in[4];
    const float* be1 = (const float*)d_in[5];
    const float* W2  = (const float*)d_in[6];
    const float* b2  = (const float*)d_in[7];
    const float* g2  = (const float*)d_in[8];
    const float* be2 = (const float*)d_in[9];
    const float* W3  = (const float*)d_in[10];
    const float* b3  = (const float*)d_in[11];
    int E = in_sizes[1] / 2;
    const int* src = ei;
    const int* dst = ei + E;
    float* out = (float*)d_out;

    void *pA, *pB, *pH3, *pG3, *pS, *pSc, *pSh;
    cudaGetSymbolAddress(&pA,  g_bufA);
    cudaGetSymbolAddress(&pB,  g_bufB);
    cudaGetSymbolAddress(&pH3, g_hw3);
    cudaGetSymbolAddress(&pG3, g_agg3);
    cudaGetSymbolAddress(&pS,  g_sums);
    cudaGetSymbolAddress(&pSc, g_scale);
    cudaGetSymbolAddress(&pSh, g_shift);
    float4* bufA = (float4*)pA;
    float4* bufB = (float4*)pB;
    float4* hw3  = (float4*)pH3;
    float4* agg3 = (float4*)pG3;
    float* sums  = (float*)pS;
    float* scale = (float*)pSc;
    float* shift = (float*)pSh;

    const int n4_128 = NNODES * 32;
    const int GB128  = n4_128 / 256;
    const int GN     = (NNODES + 255) / 256;
    const int GE     = (E + 255) / 256;
    const int GROW   = (NNODES + 7) / 8;
    const int GM     = (NNODES + 127) / 128;

    // preprocessing (tf32 sgemm1 kept at launch #4 so ncu captures it)
    k_zero  <<<GN, 256>>>();
    k_degree<<<GE, 256>>>(dst, E);
    k_keys  <<<1, 32>>>();
    sgemm_tf32<16><<<GM, 256>>>(x, W1, (float*)bufA, NNODES, 128);
    k_dinv      <<<GN, 256>>>();
    k_scan_local<<<SCAN_BLOCKS, 256>>>();
    k_scan_block<<<1, 512>>>();
    k_scan_add  <<<SCAN_BLOCKS, 256>>>(E);
    k_fill      <<<GE, 256>>>(src, dst, E);

    // ---- layer 1 ----
    spmm128 <<<GROW, 256>>>(bufA, bufB, b1);
    k_bnstats<<<400, 256>>>((const float*)bufB, sums);
    k_bnfinal<<<1, 128>>>(sums, g1, be1, scale, shift);
    k_bndrop<<<GB128, 256>>>(bufB, bufA, scale, shift, 0, n4_128);

    // ---- layer 2 ----
    sgemm_tf32<16><<<GM, 256>>>((const float*)bufA, W2, (float*)bufB, NNODES, 128);
    spmm128 <<<GROW, 256>>>(bufB, bufA, b2);
    k_bnstats<<<400, 256>>>((const float*)bufA, sums + 256);
    k_bnfinal<<<1, 128>>>(sums + 256, g2, be2, scale + 128, shift + 128);
    k_bndrop<<<GB128, 256>>>(bufA, bufB, scale + 128, shift + 128, 1, n4_128);

    // ---- layer 3 + log_softmax ----
    sgemm_tf32<5><<<GM, 256>>>((const float*)bufB, W3, (float*)hw3, NNODES, 40);
    spmm40  <<<GROW, 256>>>(hw3, agg3, b3);
    k_logsoftmax<<<GROW, 256>>>((const float*)agg3, out, NNODES);
}

// round 7
// speedup vs baseline: 1.0486x; 1.0486x over previous
#include <cuda_runtime.h>
#include <cstdint>

#define NNODES 100000
#define MAXE   1000000

// ---------------- scratch (static __device__ globals; no allocation) -------
__device__ __align__(16) float4 g_bufA[NNODES * 32];   // 100000 x 128 floats
__device__ __align__(16) float4 g_bufB[NNODES * 32];   // 100000 x 128 floats
__device__ __align__(16) float4 g_hw3 [NNODES * 10];   // 100000 x 40 floats
__device__ __align__(16) float4 g_agg3[NNODES * 10];   // 100000 x 40 floats
__device__ float g_dinv[NNODES];
__device__ int   g_icnt[NNODES];
__device__ int   g_fc  [NNODES];
__device__ int   g_rs  [NNODES + 1];
__device__ int   g_perm[MAXE];
__device__ int   g_bsum[512];
__device__ int   g_boff[512];
__device__ float g_sums[512];
__device__ __align__(16) float g_scale[256];
__device__ __align__(16) float g_shift[256];
__device__ unsigned g_keys[4];

#define SCAN_BLOCKS 391

// ---------------- threefry2x32 (JAX-exact, 20 rounds) ----------------------
__device__ __forceinline__ void tf_round(uint32_t &x0, uint32_t &x1, int r) {
    x0 += x1;
    x1 = __funnelshift_l(x1, x1, r);
    x1 ^= x0;
}

__device__ __forceinline__ uint2 tf_full(uint32_t k0, uint32_t k1, uint32_t x0, uint32_t x1) {
    uint32_t k2 = k0 ^ k1 ^ 0x1BD11BDAu;
    x0 += k0; x1 += k1;
    tf_round(x0,x1,13); tf_round(x0,x1,15); tf_round(x0,x1,26); tf_round(x0,x1,6);
    x0 += k1; x1 += k2 + 1u;
    tf_round(x0,x1,17); tf_round(x0,x1,29); tf_round(x0,x1,16); tf_round(x0,x1,24);
    x0 += k2; x1 += k0 + 2u;
    tf_round(x0,x1,13); tf_round(x0,x1,15); tf_round(x0,x1,26); tf_round(x0,x1,6);
    x0 += k0; x1 += k1 + 3u;
    tf_round(x0,x1,17); tf_round(x0,x1,29); tf_round(x0,x1,16); tf_round(x0,x1,24);
    x0 += k1; x1 += k2 + 4u;
    tf_round(x0,x1,13); tf_round(x0,x1,15); tf_round(x0,x1,26); tf_round(x0,x1,6);
    x0 += k2; x1 += k0 + 5u;
    return make_uint2(x0, x1);
}

__device__ __forceinline__ uint32_t tf_bits_xor(uint32_t k0, uint32_t k1, uint32_t k2, uint32_t ctr) {
    uint32_t x0 = k0;
    uint32_t x1 = ctr + k1;
    tf_round(x0,x1,13); tf_round(x0,x1,15); tf_round(x0,x1,26); tf_round(x0,x1,6);
    x0 += k1; x1 += k2 + 1u;
    tf_round(x0,x1,17); tf_round(x0,x1,29); tf_round(x0,x1,16); tf_round(x0,x1,24);
    x0 += k2; x1 += k0 + 2u;
    tf_round(x0,x1,13); tf_round(x0,x1,15); tf_round(x0,x1,26); tf_round(x0,x1,6);
    x0 += k0; x1 += k1 + 3u;
    tf_round(x0,x1,17); tf_round(x0,x1,29); tf_round(x0,x1,16); tf_round(x0,x1,24);
    x0 += k1; x1 += k2 + 4u;
    tf_round(x0,x1,13); tf_round(x0,x1,15); tf_round(x0,x1,26); tf_round(x0,x1,6);
    x0 += k2; x1 += k0 + 5u;
    return x0 ^ x1;
}

__global__ void k_keys() {
    if (threadIdx.x == 0) {
        uint2 a = tf_full(0u, 42u, 0u, 0u);
        uint2 b = tf_full(0u, 42u, 0u, 1u);
        g_keys[0] = a.x; g_keys[1] = a.y;
        g_keys[2] = b.x; g_keys[3] = b.y;
    }
}

// ---------------- graph preprocessing --------------------------------------
__global__ void k_zero() {
    int i = blockIdx.x * 256 + threadIdx.x;
    if (i < NNODES) { g_icnt[i] = 0; g_fc[i] = 0; }
    if (i < 512)    g_sums[i] = 0.f;
}

__global__ void k_degree(const int* __restrict__ dst, int E) {
    int e = blockIdx.x * 256 + threadIdx.x;
    if (e < E) atomicAdd(&g_icnt[dst[e]], 1);
}

__global__ void k_dinv() {
    int i = blockIdx.x * 256 + threadIdx.x;
    if (i < NNODES) g_dinv[i] = rsqrtf((float)g_icnt[i] + 1.0f);
}

__global__ __launch_bounds__(256) void k_scan_local() {
    __shared__ int s[256];
    int t = threadIdx.x;
    int i = blockIdx.x * 256 + t;
    int v = (i < NNODES) ? g_icnt[i] : 0;
    s[t] = v;
    __syncthreads();
#pragma unroll
    for (int off = 1; off < 256; off <<= 1) {
        int add = (t >= off) ? s[t - off] : 0;
        __syncthreads();
        s[t] += add;
        __syncthreads();
    }
    if (i < NNODES) g_rs[i] = s[t] - v;
    if (t == 255) g_bsum[blockIdx.x] = s[255];
}

__global__ __launch_bounds__(512) void k_scan_block() {
    __shared__ int s[512];
    int t = threadIdx.x;
    int v = (t < SCAN_BLOCKS) ? g_bsum[t] : 0;
    s[t] = v;
    __syncthreads();
#pragma unroll
    for (int off = 1; off < 512; off <<= 1) {
        int add = (t >= off) ? s[t - off] : 0;
        __syncthreads();
        s[t] += add;
        __syncthreads();
    }
    g_boff[t] = s[t] - v;
}

__global__ void k_scan_add(int E) {
    int i = blockIdx.x * 256 + threadIdx.x;
    if (i < NNODES) g_rs[i] += g_boff[blockIdx.x];
    if (i == NNODES) g_rs[NNODES] = E;
}

__global__ void k_fill(const int* __restrict__ src, const int* __restrict__ dst, int E) {
    int e = blockIdx.x * 256 + threadIdx.x;
    if (e >= E) return;
    int d = dst[e];
    int pos = g_rs[d] + atomicAdd(&g_fc[d], 1);
    g_perm[pos] = src[e];
}

// ---------------- TF32 split-MMA GEMM, packed LDS.128 fragments -------------
// 3xTF32: a=ahi+alo, b=bhi+blo; D += ahi*bhi + alo*bhi + ahi*blo (err ~2^-22)
// Block tile 128xNCPAD, 8 warps as 4m x 2n (warp: 32 rows x NCPAD/2 cols).
// Smem layout packs (hi[k],hi[k+4],lo[k],lo[k+4]) per float4 so every fragment
// fetch is a single conflict-free LDS.128 (t-slice stride padded to NCPAD+2).
__device__ __forceinline__ uint32_t f2tf32(float x) {
    uint32_t r;
    asm("cvt.rna.tf32.f32 %0, %1;" : "=r"(r) : "f"(x));
    return r;
}
__device__ __forceinline__ float f2tf32f(float x) {
    return __uint_as_float(f2tf32(x));
}

#define MMA_TF32(cc, a0,a1,a2,a3, b0,b1)                                       \
    asm volatile("mma.sync.aligned.m16n8k8.row.col.f32.tf32.tf32.f32 "         \
                 "{%0,%1,%2,%3}, {%4,%5,%6,%7}, {%8,%9}, {%0,%1,%2,%3};"       \
                 : "+f"(cc[0]), "+f"(cc[1]), "+f"(cc[2]), "+f"(cc[3])          \
                 : "r"(a0), "r"(a1), "r"(a2), "r"(a3), "r"(b0), "r"(b1))

template<int NCPAD>
__global__ __launch_bounds__(256) void sgemm_tf32p(
    const float* __restrict__ A, const float* __restrict__ B,
    float* __restrict__ C, int M, int NC)
{
    constexpr int NT = NCPAD / 16;            // n-tiles of 8 per warp
    __shared__ float4 Ap[2][4][130];
    __shared__ float4 Bp[2][4][NCPAD + 2];

    int tid  = threadIdx.x;
    int warp = tid >> 5, lane = tid & 31;
    int wm = warp >> 1, wn = warp & 1;
    int gid = lane >> 2, ctid = lane & 3;
    int row0 = blockIdx.x * 128;
    int wr = wm * 32;
    int wc = wn * (NCPAD / 2);

    float c[2][NT][4];
#pragma unroll
    for (int mt = 0; mt < 2; mt++)
#pragma unroll
        for (int nt = 0; nt < NT; nt++)
#pragma unroll
            for (int j = 0; j < 4; j++) c[mt][nt][j] = 0.f;

    int ar = tid >> 1;         // 0..127 row
    int ag = tid & 1;          // k-half

    for (int k0 = 0; k0 < 128; k0 += 16) {
        // ---- stage A: hi/lo packed ----
        {
            float4 v0 = make_float4(0.f,0.f,0.f,0.f), v1 = v0;
            int gr = row0 + ar;
            if (gr < M) {
                v0 = *(const float4*)(A + gr * 128 + k0 + ag * 8);
                v1 = *(const float4*)(A + gr * 128 + k0 + ag * 8 + 4);
            }
            float vv[8] = {v0.x, v0.y, v0.z, v0.w, v1.x, v1.y, v1.z, v1.w};
            float h[8], l[8];
#pragma unroll
            for (int t = 0; t < 8; t++) {
                h[t] = f2tf32f(vv[t]);
                l[t] = f2tf32f(vv[t] - h[t]);
            }
#pragma unroll
            for (int t = 0; t < 4; t++)
                Ap[ag][t][ar] = make_float4(h[t], h[t + 4], l[t], l[t + 4]);
        }
        // ---- stage B: hi/lo packed ----
        for (int idx = tid; idx < 8 * NCPAD; idx += 256) {
            int cc   = idx & (NCPAD - 1);
            int rest = idx / NCPAD;          // 0..7
            int bg = rest & 1, bt = rest >> 1;
            int k = k0 + bg * 8 + bt;
            float bva = (cc < NC) ? B[k * NC + cc] : 0.f;
            float bvb = (cc < NC) ? B[(k + 4) * NC + cc] : 0.f;
            float bh0 = f2tf32f(bva), bh1 = f2tf32f(bvb);
            Bp[bg][bt][cc] = make_float4(bh0, bh1, f2tf32f(bva - bh0), f2tf32f(bvb - bh1));
        }
        __syncthreads();

#pragma unroll
        for (int g = 0; g < 2; g++) {
            float4 alo0 = Ap[g][ctid][wr + gid];
            float4 ahi0 = Ap[g][ctid][wr + gid + 8];
            float4 alo1 = Ap[g][ctid][wr + 16 + gid];
            float4 ahi1 = Ap[g][ctid][wr + 16 + gid + 8];
            uint32_t ah0[4] = {__float_as_uint(alo0.x), __float_as_uint(ahi0.x),
                               __float_as_uint(alo0.y), __float_as_uint(ahi0.y)};
            uint32_t al0[4] = {__float_as_uint(alo0.z), __float_as_uint(ahi0.z),
                               __float_as_uint(alo0.w), __float_as_uint(ahi0.w)};
            uint32_t ah1[4] = {__float_as_uint(alo1.x), __float_as_uint(ahi1.x),
                               __float_as_uint(alo1.y), __float_as_uint(ahi1.y)};
            uint32_t al1[4] = {__float_as_uint(alo1.z), __float_as_uint(ahi1.z),
                               __float_as_uint(alo1.w), __float_as_uint(ahi1.w)};
#pragma unroll
            for (int nt = 0; nt < NT; nt++) {
                float4 b = Bp[g][ctid][wc + nt * 8 + gid];
                uint32_t bh0 = __float_as_uint(b.x), bh1 = __float_as_uint(b.y);
                uint32_t bl0 = __float_as_uint(b.z), bl1 = __float_as_uint(b.w);
                MMA_TF32(c[0][nt], ah0[0], ah0[1], ah0[2], ah0[3], bh0, bh1);
                MMA_TF32(c[0][nt], al0[0], al0[1], al0[2], al0[3], bh0, bh1);
                MMA_TF32(c[0][nt], ah0[0], ah0[1], ah0[2], ah0[3], bl0, bl1);
                MMA_TF32(c[1][nt], ah1[0], ah1[1], ah1[2], ah1[3], bh0, bh1);
                MMA_TF32(c[1][nt], al1[0], al1[1], al1[2], al1[3], bh0, bh1);
                MMA_TF32(c[1][nt], ah1[0], ah1[1], ah1[2], ah1[3], bl0, bl1);
            }
        }
        __syncthreads();
    }

#pragma unroll
    for (int mt = 0; mt < 2; mt++) {
        int r0 = row0 + wr + mt * 16 + gid;
        int r1 = r0 + 8;
#pragma unroll
        for (int nt = 0; nt < NT; nt++) {
            int ccol = wc + nt * 8 + ctid * 2;
            if (ccol < NC) {
                if (r0 < M) *(float2*)(C + r0 * NC + ccol) = make_float2(c[mt][nt][0], c[mt][nt][1]);
                if (r1 < M) *(float2*)(C + r1 * NC + ccol) = make_float2(c[mt][nt][2], c[mt][nt][3]);
            }
        }
    }
}

// ---------------- CSR SpMM (no atomics): agg = Anorm*hw + self + bias ------
__global__ __launch_bounds__(256) void spmm128(
    const float4* __restrict__ hw, float4* __restrict__ agg,
    const float* __restrict__ bias)
{
    int row = blockIdx.x * 8 + (threadIdx.x >> 5);
    if (row >= NNODES) return;
    int lane = threadIdx.x & 31;
    int beg = __ldg(&g_rs[row]);
    int end = __ldg(&g_rs[row + 1]);
    float di = g_dinv[row];
    float di2 = di * di;

    float4 self = __ldg(hw + row * 32 + lane);
    float4 b = ((const float4*)bias)[lane];
    float4 acc  = make_float4(fmaf(self.x, di2, b.x), fmaf(self.y, di2, b.y),
                              fmaf(self.z, di2, b.z), fmaf(self.w, di2, b.w));
    float4 acc2 = make_float4(0.f, 0.f, 0.f, 0.f);

    int j = beg;
    for (; j + 1 < end; j += 2) {
        int s0 = __ldg(&g_perm[j]);
        int s1 = __ldg(&g_perm[j + 1]);
        float n0 = __ldg(&g_dinv[s0]) * di;
        float n1 = __ldg(&g_dinv[s1]) * di;
        float4 v0 = __ldg(hw + s0 * 32 + lane);
        float4 v1 = __ldg(hw + s1 * 32 + lane);
        acc.x  = fmaf(v0.x, n0, acc.x);  acc.y  = fmaf(v0.y, n0, acc.y);
        acc.z  = fmaf(v0.z, n0, acc.z);  acc.w  = fmaf(v0.w, n0, acc.w);
        acc2.x = fmaf(v1.x, n1, acc2.x); acc2.y = fmaf(v1.y, n1, acc2.y);
        acc2.z = fmaf(v1.z, n1, acc2.z); acc2.w = fmaf(v1.w, n1, acc2.w);
    }
    if (j < end) {
        int s0 = __ldg(&g_perm[j]);
        float n0 = __ldg(&g_dinv[s0]) * di;
        float4 v0 = __ldg(hw + s0 * 32 + lane);
        acc.x = fmaf(v0.x, n0, acc.x); acc.y = fmaf(v0.y, n0, acc.y);
        acc.z = fmaf(v0.z, n0, acc.z); acc.w = fmaf(v0.w, n0, acc.w);
    }
    agg[row * 32 + lane] = make_float4(acc.x + acc2.x, acc.y + acc2.y,
                                       acc.z + acc2.z, acc.w + acc2.w);
}

__global__ __launch_bounds__(256) void spmm40(
    const float4* __restrict__ hw, float4* __restrict__ agg,
    const float* __restrict__ bias)
{
    int row = blockIdx.x * 8 + (threadIdx.x >> 5);
    if (row >= NNODES) return;
    int lane = threadIdx.x & 31;
    if (lane >= 10) return;
    int beg = __ldg(&g_rs[row]);
    int end = __ldg(&g_rs[row + 1]);
    float di = g_dinv[row];
    float di2 = di * di;

    float4 self = __ldg(hw + row * 10 + lane);
    float4 b = ((const float4*)bias)[lane];
    float4 acc = make_float4(fmaf(self.x, di2, b.x), fmaf(self.y, di2, b.y),
                             fmaf(self.z, di2, b.z), fmaf(self.w, di2, b.w));
    for (int j = beg; j < end; j++) {
        int s = __ldg(&g_perm[j]);
        float n = __ldg(&g_dinv[s]) * di;
        float4 v = __ldg(hw + s * 10 + lane);
        acc.x = fmaf(v.x, n, acc.x); acc.y = fmaf(v.y, n, acc.y);
        acc.z = fmaf(v.z, n, acc.z); acc.w = fmaf(v.w, n, acc.w);
    }
    agg[row * 10 + lane] = acc;
}

// ---------------- batchnorm stats + finalize -------------------------------
__global__ __launch_bounds__(256) void k_bnstats(const float* __restrict__ h,
                                                 float* __restrict__ sums) {
    __shared__ float ss[256], sq[256];
    int tid = threadIdx.x;
    int c = tid & 127;
    int half = tid >> 7;
    int rbeg = blockIdx.x * 250;
    float s = 0.f, q = 0.f;
    for (int r = rbeg + half; r < rbeg + 250; r += 2) {
        float v = h[r * 128 + c];
        s += v;
        q = fmaf(v, v, q);
    }
    ss[tid] = s; sq[tid] = q;
    __syncthreads();
    if (half == 0) {
        atomicAdd(&sums[c],       ss[tid] + ss[tid + 128]);
        atomicAdd(&sums[128 + c], sq[tid] + sq[tid + 128]);
    }
}

__global__ void k_bnfinal(const float* __restrict__ sums,
                          const float* __restrict__ gamma, const float* __restrict__ beta,
                          float* __restrict__ sc, float* __restrict__ sh) {
    int c = threadIdx.x;
    const float inv_n = 1.0f / (float)NNODES;
    float mean = sums[c] * inv_n;
    float var  = sums[128 + c] * inv_n - mean * mean;
    var = fmaxf(var, 0.f);
    float rstd = rsqrtf(var + 1e-5f);
    float a = gamma[c] * rstd;
    sc[c] = a;
    sh[c] = beta[c] - mean * a;
}

// ---------------- fused BN + ReLU + exact threefry dropout -----------------
__global__ __launch_bounds__(256) void k_bndrop(
    const float4* __restrict__ in, float4* __restrict__ out,
    const float* __restrict__ sc, const float* __restrict__ sh,
    int layer, int n4)
{
    int t = blockIdx.x * 256 + threadIdx.x;
    if (t >= n4) return;
    uint32_t k0 = g_keys[layer * 2 + 0];
    uint32_t k1 = g_keys[layer * 2 + 1];
    uint32_t k2 = k0 ^ k1 ^ 0x1BD11BDAu;

    int c = (t & 31) * 4;
    float4 v = in[t];
    float4 a = *(const float4*)(sc + c);
    float4 b = *(const float4*)(sh + c);

    float r0 = fmaxf(fmaf(v.x, a.x, b.x), 0.f);
    float r1 = fmaxf(fmaf(v.y, a.y, b.y), 0.f);
    float r2 = fmaxf(fmaf(v.z, a.z, b.z), 0.f);
    float r3 = fmaxf(fmaf(v.w, a.w, b.w), 0.f);

    uint32_t i0 = (uint32_t)t * 4u;
    uint32_t m0 = tf_bits_xor(k0, k1, k2, i0 + 0u);
    uint32_t m1 = tf_bits_xor(k0, k1, k2, i0 + 1u);
    uint32_t m2 = tf_bits_xor(k0, k1, k2, i0 + 2u);
    uint32_t m3 = tf_bits_xor(k0, k1, k2, i0 + 3u);

    v.x = (m0 & 0x80000000u) ? 0.f : r0 + r0;
    v.y = (m1 & 0x80000000u) ? 0.f : r1 + r1;
    v.z = (m2 & 0x80000000u) ? 0.f : r2 + r2;
    v.w = (m3 & 0x80000000u) ? 0.f : r3 + r3;
    out[t] = v;
}

// ---------------- log_softmax over 40 cols (warp per row) ------------------
__global__ __launch_bounds__(256) void k_logsoftmax(const float* __restrict__ in,
                                                    float* __restrict__ out, int n) {
    int r = blockIdx.x * 8 + (threadIdx.x >> 5);
    if (r >= n) return;
    int lane = threadIdx.x & 31;
    float v0 = __ldg(in + r * 40 + lane);
    float v1 = (lane < 8) ? __ldg(in + r * 40 + 32 + lane) : -3.4e38f;
    float mx = fmaxf(v0, v1);
#pragma unroll
    for (int o = 16; o; o >>= 1) mx = fmaxf(mx, __shfl_xor_sync(0xffffffffu, mx, o));
    float s = expf(v0 - mx) + ((lane < 8) ? expf(v1 - mx) : 0.f);
#pragma unroll
    for (int o = 16; o; o >>= 1) s += __shfl_xor_sync(0xffffffffu, s, o);
    float l = mx + logf(s);
    out[r * 40 + lane] = v0 - l;
    if (lane < 8) out[r * 40 + 32 + lane] = v1 - l;
}

// ---------------- launch ---------------------------------------------------
extern "C" void kernel_launch(void* const* d_in, const int* in_sizes, int n_in,
                              void* d_out, int out_size) {
    const float* x   = (const float*)d_in[0];
    const int*   ei  = (const int*)  d_in[1];
    const float* W1  = (const float*)d_in[2];
    const float* b1  = (const float*)d_in[3];
    const float* g1  = (const float*)d_in[4];
    const float* be1 = (const float*)d_in[5];
    const float* W2  = (const float*)d_in[6];
    const float* b2  = (const float*)d_in[7];
    const float* g2  = (const float*)d_in[8];
    const float* be2 = (const float*)d_in[9];
    const float* W3  = (const float*)d_in[10];
    const float* b3  = (const float*)d_in[11];
    int E = in_sizes[1] / 2;
    const int* src = ei;
    const int* dst = ei + E;
    float* out = (float*)d_out;

    void *pA, *pB, *pH3, *pG3, *pS, *pSc, *pSh;
    cudaGetSymbolAddress(&pA,  g_bufA);
    cudaGetSymbolAddress(&pB,  g_bufB);
    cudaGetSymbolAddress(&pH3, g_hw3);
    cudaGetSymbolAddress(&pG3, g_agg3);
    cudaGetSymbolAddress(&pS,  g_sums);
    cudaGetSymbolAddress(&pSc, g_scale);
    cudaGetSymbolAddress(&pSh, g_shift);
    float4* bufA = (float4*)pA;
    float4* bufB = (float4*)pB;
    float4* hw3  = (float4*)pH3;
    float4* agg3 = (float4*)pG3;
    float* sums  = (float*)pS;
    float* scale = (float*)pSc;
    float* shift = (float*)pSh;

    const int n4_128 = NNODES * 32;
    const int GB128  = n4_128 / 256;
    const int GN     = (NNODES + 255) / 256;
    const int GE     = (E + 255) / 256;
    const int GROW   = (NNODES + 7) / 8;
    const int GM     = (NNODES + 127) / 128;

    // preprocessing (gemm1 kept at launch #4 so ncu captures it)
    k_zero  <<<GN, 256>>>();
    k_degree<<<GE, 256>>>(dst, E);
    k_keys  <<<1, 32>>>();
    sgemm_tf32p<128><<<GM, 256>>>(x, W1, (float*)bufA, NNODES, 128);
    k_dinv      <<<GN, 256>>>();
    k_scan_local<<<SCAN_BLOCKS, 256>>>();
    k_scan_block<<<1, 512>>>();
    k_scan_add  <<<SCAN_BLOCKS, 256>>>(E);
    k_fill      <<<GE, 256>>>(src, dst, E);

    // ---- layer 1 ----
    spmm128 <<<GROW, 256>>>(bufA, bufB, b1);
    k_bnstats<<<400, 256>>>((const float*)bufB, sums);
    k_bnfinal<<<1, 128>>>(sums, g1, be1, scale, shift);
    k_bndrop<<<GB128, 256>>>(bufB, bufA, scale, shift, 0, n4_128);

    // ---- layer 2 ----
    sgemm_tf32p<128><<<GM, 256>>>((const float*)bufA, W2, (float*)bufB, NNODES, 128);
    spmm128 <<<GROW, 256>>>(bufB, bufA, b2);
    k_bnstats<<<400, 256>>>((const float*)bufA, sums + 256);
    k_bnfinal<<<1, 128>>>(sums + 256, g2, be2, scale + 128, shift + 128);
    k_bndrop<<<GB128, 256>>>(bufA, bufB, scale + 128, shift + 128, 1, n4_128);

    // ---- layer 3 + log_softmax ----
    sgemm_tf32p<64><<<GM, 256>>>((const float*)bufB, W3, (float*)hw3, NNODES, 40);
    spmm40  <<<GROW, 256>>>(hw3, agg3, b3);
    k_logsoftmax<<<GROW, 256>>>((const float*)agg3, out, NNODES);
}